// round 16
// baseline (speedup 1.0000x reference)
#include <cuda_runtime.h>
#include <stdint.h>

#define NB 4          // batch
#define MB 50         // gt boxes per batch
#define PMB 52        // padded boxes per batch (2 degenerate pads; 52*4B = 16B-aligned)
#define KB 240000     // anchors
#define NK (NB*KB)
#define SELK 256      // NUM_FG == NUM_BG
#define NBINS 4096    // 12-bit first-stage radix
#define CAP 8192      // candidate buffer per selection

// r-space thresholds: iou>=0.7 <=> r>=7/17 ; iou<0.3 <=> r<3/13  (r = inter/S, iou = r/(1-r))
#define R_POS 0.411764706f
#define R_NEG 0.230769231f
#define R_MARGIN 1e-5f

// ---------------- persistent scratch (no allocations allowed) ----------------
__device__ uint8_t      g_flags[NK];          // 0 none, 1 pos, 2 neg
__device__ unsigned int g_hist[8][NBINS];     // zero-init; cleared by final's last block
__device__ unsigned int g_prefix[8];
__device__ int          g_kk[8];
__device__ int          g_done[8];
__device__ unsigned int g_cnt[8];             // cleared by final's last block
__device__ unsigned int g_cand[8][CAP];
__device__ int          g_cidx[8][CAP];
__device__ unsigned int g_tick;               // ticket (self-resetting)

__device__ __forceinline__ unsigned int fkey(float f) {
    unsigned int u = __float_as_uint(f);
    return (u & 0x80000000u) ? ~u : (u | 0x80000000u);  // order-preserving
}

__device__ __forceinline__ float frcp_approx(float x) {
    float r; asm("rcp.approx.f32 %0, %1;" : "=f"(r) : "f"(x)); return r;
}

__device__ __forceinline__ unsigned int warp_suffix(unsigned int v, int lane) {
    #pragma unroll
    for (int off = 1; off < 32; off <<= 1) {
        unsigned int x = __shfl_down_sync(0xFFFFFFFFu, v, off);
        if (lane + off < 32) v += x;
    }
    return v;
}

// ======== K1: approx max-r fast loop (float4 S-chunks); division-free exact redo ========
__global__ void __launch_bounds__(256, 8) at_main_kernel(
        const float4* __restrict__ anchors,
        const float4* __restrict__ gt_boxes,
        const int*    __restrict__ gt_labels,
        const float*  __restrict__ scores,
        float*        __restrict__ out) {
    __shared__ __align__(16) float4 s_gt[NB * PMB];
    __shared__ __align__(16) float  s_S[NB * PMB];   // area_g + 1e-8 (fast path; pads = 1.0)
    __shared__ float  s_ag[NB * PMB];  // raw area_g (exact path)
    __shared__ float  s_lab[NB * PMB];

    {
        const int i = threadIdx.x;
        if (i < NB * MB) {                       // real entries
            const int n = i / MB, m = i - n * MB;
            const int j = n * PMB + m;
            float4 g = gt_boxes[i];
            s_gt[j]  = g;
            float ag = __fmul_rn(__fsub_rn(g.z, g.x), __fsub_rn(g.w, g.y));
            s_ag[j]  = ag;
            s_S[j]   = __fadd_rn(ag, 1e-8f);
            s_lab[j] = (float)gt_labels[i];
        } else if (i < NB * MB + NB * (PMB - MB)) {   // 8 degenerate pads
            const int p = i - NB * MB;
            const int j = (p >> 1) * PMB + MB + (p & 1);
            s_gt[j]  = make_float4(0.f, 0.f, 0.f, 0.f);   // inter = 0 for any anchor
            s_ag[j]  = 0.f;
            s_S[j]   = 1.0f;
            s_lab[j] = 0.f;
        }
    }
    __syncthreads();

    const int k = blockIdx.x * 256 + threadIdx.x;
    if (k >= KB) return;

    const float4 a = anchors[k];                  // loaded ONCE for all 4 batches
    const float area_a = __fmul_rn(__fsub_rn(a.z, a.x), __fsub_rn(a.w, a.y));

    #pragma unroll 1
    for (int n = 0; n < NB; ++n) {
        const float4* gt  = s_gt + n * PMB;
        const float4* S4p = (const float4*)(s_S + n * PMB);   // PMB*4B is 16B-aligned

        // ---- lean fast loop: qmax = max_m inter/S; S loaded in float4 chunks ----
        float qmax = 0.f;                        // q >= 0 always; pads give q = 0
        #pragma unroll
        for (int c = 0; c < PMB / 4; ++c) {
            const float4 S4 = S4p[c];
            #pragma unroll
            for (int j = 0; j < 4; ++j) {
                const int m = c * 4 + j;
                const float S = (j == 0) ? S4.x : (j == 1) ? S4.y : (j == 2) ? S4.z : S4.w;
                float4 g = gt[m];
                float w = fmaxf(__fsub_rn(fminf(a.z, g.z), fmaxf(a.x, g.x)), 0.f);
                float h = fmaxf(__fsub_rn(fminf(a.w, g.w), fmaxf(a.y, g.y)), 0.f);
                float q = __fmul_rn(__fmul_rn(w, h), frcp_approx(area_a + S));
                qmax = fmaxf(qmax, q);
            }
        }

        const int idx = n * KB + k;
        uint8_t f;
        float   cls = 0.f;
        float4  r = make_float4(0.f, 0.f, 0.f, 0.f);

        const bool need_exact = (qmax >= R_POS - R_MARGIN) |
                                (fabsf(qmax - R_NEG) <= R_MARGIN);
        if (__builtin_expect(need_exact, 0)) {
            // ---- division-FREE exact redo over the 50 REAL boxes (cross-mult argmax) ----
            const float* ag_v = s_ag + n * PMB;
            float bi, bden; int bm = 0; bool tie = false;
            {
                float4 g = gt[0];
                float w = fmaxf(__fsub_rn(fminf(a.z, g.z), fmaxf(a.x, g.x)), 0.f);
                float h = fmaxf(__fsub_rn(fminf(a.w, g.w), fmaxf(a.y, g.y)), 0.f);
                bi   = __fmul_rn(w, h);
                bden = __fadd_rn(__fsub_rn(__fadd_rn(area_a, ag_v[0]), bi), 1e-8f);
            }
            #pragma unroll 5
            for (int m = 1; m < MB; ++m) {
                float4 g = gt[m];
                float w = fmaxf(__fsub_rn(fminf(a.z, g.z), fmaxf(a.x, g.x)), 0.f);
                float h = fmaxf(__fsub_rn(fminf(a.w, g.w), fmaxf(a.y, g.y)), 0.f);
                float inter = __fmul_rn(w, h);
                float den = __fadd_rn(__fsub_rn(__fadd_rn(area_a, ag_v[m]), inter), 1e-8f);
                float lhs  = __fmul_rn(inter, bden);
                float rhs  = __fmul_rn(bi, den);
                float diff = lhs - rhs;
                tie |= (fabsf(diff) < 5e-6f * fmaxf(lhs, rhs));
                bool better = diff > 0.f;
                bi   = better ? inter : bi;
                bden = better ? den   : bden;
                bm   = better ? m     : bm;
            }
            float max_o;
            if (__builtin_expect(tie, 0)) {
                // ultra-rare: full reference redo with per-m divisions
                max_o = -1.f; bm = 0;
                for (int m = 0; m < MB; ++m) {
                    float4 g = gt[m];
                    float w = fmaxf(__fsub_rn(fminf(a.z, g.z), fmaxf(a.x, g.x)), 0.f);
                    float h = fmaxf(__fsub_rn(fminf(a.w, g.w), fmaxf(a.y, g.y)), 0.f);
                    float inter = __fmul_rn(w, h);
                    float den = __fadd_rn(__fsub_rn(__fadd_rn(area_a, ag_v[m]), inter), 1e-8f);
                    float io  = __fdiv_rn(inter, den);
                    if (io > max_o) { max_o = io; bm = m; }
                }
            } else {
                max_o = __fdiv_rn(bi, bden);   // exact reference max IoU
            }
            const bool pos = max_o >= 0.7f;
            const bool neg = max_o <  0.3f;
            f = pos ? (uint8_t)1 : (neg ? (uint8_t)2 : (uint8_t)0);
            if (pos) {
                cls = s_lab[n * PMB + bm];
                const float aw  = a.z - a.x,        ah  = a.w - a.y;
                const float acx = a.x + 0.5f * aw,  acy = a.y + 0.5f * ah;
                float4 g  = gt[bm];
                float gw  = g.z - g.x,       gh  = g.w - g.y;
                float gcx = g.x + 0.5f * gw, gcy = g.y + 0.5f * gh;
                r.x = (gcx - acx) / aw;
                r.y = (gcy - acy) / ah;
                r.z = logf(gw / aw);
                r.w = logf(gh / ah);
            }
        } else {
            f = (qmax < R_NEG) ? (uint8_t)2 : (uint8_t)0;
        }

        g_flags[idx] = f;
        out[idx] = cls;
        ((float4*)(out + NK))[idx] = r;

        if (f) {  // fused 12-bit radix histogram (top 12 key bits)
            unsigned int key = fkey(__ldg(&scores[idx]));
            atomicAdd(&g_hist[n * 2 + (int)(f - 1)][key >> 20], 1u);
        }
    }
}

// ======== K2: pick 12-bit threshold bin per selection (register-resident pick) ========
__global__ void __launch_bounds__(256) at_scanA_kernel() {
    cudaGridDependencySynchronize();        // PDL: wait for at_main's hist
    const int sel = blockIdx.x;
    const int t   = threadIdx.x;            // 256 threads × 16 bins
    const unsigned int* __restrict__ h = g_hist[sel];
    __shared__ unsigned int s[256];

    unsigned int v[16];
    const int base = t * 16;
    unsigned int sum = 0;
    #pragma unroll
    for (int i = 0; i < 16; ++i) { v[i] = __ldg(&h[base + i]); sum += v[i]; }
    s[t] = sum;
    __syncthreads();
    #pragma unroll
    for (int off = 1; off < 256; off <<= 1) {   // inclusive suffix scan
        unsigned int x = (t + off < 256) ? s[t + off] : 0u;
        __syncthreads();
        s[t] += x;
        __syncthreads();
    }
    const unsigned int total = s[0];
    const unsigned int above = s[t] - sum;      // strictly above this chunk
    if (t == 0) g_done[sel] = (total < SELK);
    if (total >= SELK && above < SELK && above + sum >= SELK) {   // exactly one thread
        unsigned int cum = above;
        #pragma unroll
        for (int b = 15; b >= 0; --b) {
            unsigned int c = v[b];
            if (cum + c >= SELK) {
                g_prefix[sel] = (unsigned int)(base + b);
                g_kk[sel]     = (int)(SELK - cum);
                break;
            }
            cum += c;
        }
    }
}

// warp-level topbin over 1024 smem bins: lane owns bins [lane*32, lane*32+32).
__device__ __forceinline__ void warp_topbin1024(const unsigned int* h, unsigned int kk,
                                                int lane, unsigned int& bin_out,
                                                unsigned int& kk_out) {
    const int base = lane * 32;
    unsigned int v[32]; unsigned int sum = 0;
    #pragma unroll
    for (int i = 0; i < 32; ++i) { v[i] = h[base + i]; sum += v[i]; }
    unsigned int suf = warp_suffix(sum, lane);
    unsigned int above = suf - sum;                 // strictly above this lane's chunk
    bool owner = (above < kk) && (above + sum >= kk);
    unsigned int my_bin = 0, my_kk = 0;
    if (owner) {
        unsigned int cum = above;
        #pragma unroll
        for (int b = 31; b >= 0; --b) {
            if (cum + v[b] >= kk) { my_bin = (unsigned int)(base + b); my_kk = kk - cum; break; }
            cum += v[b];
        }
    }
    unsigned int mask = __ballot_sync(0xFFFFFFFFu, owner);
    int src = __ffs(mask) - 1;
    bin_out = __shfl_sync(0xFFFFFFFFu, my_bin, src);
    kk_out  = __shfl_sync(0xFFFFFFFFu, my_kk,  src);
}

// ======== K3: weights + candidate gather; last block = per-warp exact select + cleanup ====
__global__ void __launch_bounds__(256) at_final_kernel(const float* __restrict__ scores,
                                                       float* __restrict__ out) {
    cudaGridDependencySynchronize();        // PDL: wait for at_scanA's prefixes
    __shared__ unsigned int s_hist2[8][1024];   // 32KB: one 1024-bin hist per selection
    __shared__ int s_last;

    const int n = blockIdx.y;
    const int k = blockIdx.x * 256 + threadIdx.x;
    bool pushed = false;
    if (k < KB) {
        const int idx = n * KB + k;
        const uint8_t f = g_flags[idx];
        float cw = 0.f, rw = 0.f;
        if (f) {
            const int sel = n * 2 + (int)(f - 1);
            if (g_done[sel]) {
                cw = 1.f; rw = (f == 1) ? 1.f : 0.f;       // take all members
            } else {
                const unsigned int key = fkey(__ldg(&scores[idx]));
                const unsigned int hb  = key >> 20;
                const unsigned int pfx = g_prefix[sel];
                if (hb > pfx) {
                    cw = 1.f; rw = (f == 1) ? 1.f : 0.f;
                } else if (hb == pfx) {
                    unsigned int slot = atomicAdd(&g_cnt[sel], 1u);
                    if (slot < CAP) { g_cand[sel][slot] = key; g_cidx[sel][slot] = idx; }
                    pushed = true;
                }
            }
        }
        out[5 * NK + idx] = cw;
        out[6 * NK + idx] = rw;
    }
    // RARE fence: only candidate-pushing threads (~hundreds chip-wide) pay the membar.
    if (pushed) __threadfence();
    __syncthreads();
    if (threadIdx.x == 0) {
        unsigned int old = atomicAdd(&g_tick, 1u);
        s_last = (old == gridDim.x * gridDim.y - 1u);
    }
    __syncthreads();
    if (!s_last) return;
    __threadfence();

    // ---- last block: 8 warps, one selection each (no cross-warp syncs needed) ----
    const int lane = threadIdx.x & 31;
    const int sel  = threadIdx.x >> 5;
    const int c = g_done[sel] ? 0 : (int)min(g_cnt[sel], (unsigned int)CAP);
    if (c > 0) {
        unsigned int* h = s_hist2[sel];
        const unsigned int kk = (unsigned int)g_kk[sel];

        // pass 1: bits [10,20)
        #pragma unroll 8
        for (int i = lane; i < 1024; i += 32) h[i] = 0u;
        __syncwarp();
        for (int i = lane; i < c; i += 32)
            atomicAdd(&h[(g_cand[sel][i] >> 10) & 1023u], 1u);
        __syncwarp();
        unsigned int b1, k2;
        warp_topbin1024(h, kk, lane, b1, k2);

        // pass 2: bits [0,10) among candidates with mid bits == b1
        #pragma unroll 8
        for (int i = lane; i < 1024; i += 32) h[i] = 0u;
        __syncwarp();
        for (int i = lane; i < c; i += 32) {
            unsigned int key = g_cand[sel][i];
            if (((key >> 10) & 1023u) == b1) atomicAdd(&h[key & 1023u], 1u);
        }
        __syncwarp();
        unsigned int b0, dummy;
        warp_topbin1024(h, k2, lane, b0, dummy);

        // write in-bin winners (low-20 bits >= exact kth-largest low bits)
        const unsigned int thr20 = (b1 << 10) | b0;
        const float rwv = (sel & 1) ? 0.f : 1.f;     // even sel = positives
        for (int i = lane; i < c; i += 32) {
            if ((g_cand[sel][i] & 0xFFFFFu) >= thr20) {
                int idx = g_cidx[sel][i];
                out[5 * NK + idx] = 1.f;
                out[6 * NK + idx] = rwv;
            }
        }
    }

    // ---- cleanup for next graph replay ----
    __syncthreads();
    for (int i = threadIdx.x; i < 8 * NBINS; i += 256) ((unsigned int*)g_hist)[i] = 0u;
    if (threadIdx.x < 8) g_cnt[threadIdx.x] = 0u;
    if (threadIdx.x == 0) g_tick = 0u;
}

// ---------------- launch (3 kernels, PDL chain) ----------------
extern "C" void kernel_launch(void* const* d_in, const int* in_sizes, int n_in,
                              void* d_out, int out_size) {
    const float4* anchors  = (const float4*)d_in[0];   // (K,4) f32
    const float*  scores   = (const float*) d_in[1];   // (N,K) f32
    const float4* gt_boxes = (const float4*)d_in[2];   // (N,M,4) f32
    const int*    gt_lab   = (const int*)   d_in[3];   // (N,M) i32
    float* out = (float*)d_out;  // [cls_t | reg_t | cls_w | reg_w]

    const int GB = (KB + 255) / 256;   // 938
    at_main_kernel<<<GB, 256>>>(anchors, gt_boxes, gt_lab, scores, out);

    cudaLaunchAttribute attr;
    attr.id = cudaLaunchAttributeProgrammaticStreamSerialization;
    attr.val.programmaticStreamSerializationAllowed = 1;

    cudaLaunchConfig_t cfg = {};
    cfg.attrs = &attr;
    cfg.numAttrs = 1;
    cfg.blockDim = dim3(256, 1, 1);

    cfg.gridDim = dim3(8, 1, 1);
    cudaLaunchKernelEx(&cfg, at_scanA_kernel);

    cfg.gridDim = dim3(GB, NB, 1);
    cudaLaunchKernelEx(&cfg, at_final_kernel, scores, out);
}

// round 17
// speedup vs baseline: 1.0233x; 1.0233x over previous
#include <cuda_runtime.h>
#include <stdint.h>

#define NB 4          // batch
#define MB 50         // gt boxes per batch
#define KB 240000     // anchors
#define NK (NB*KB)
#define SELK 256      // NUM_FG == NUM_BG
#define NBINS 4096    // 12-bit first-stage radix
#define CAP 8192      // candidate buffer per selection

// r-space thresholds: iou>=0.7 <=> r>=7/17 ; iou<0.3 <=> r<3/13  (r = inter/S, iou = r/(1-r))
#define R_POS 0.411764706f
#define R_NEG 0.230769231f
#define R_MARGIN 1e-5f

// ---------------- persistent scratch (no allocations allowed) ----------------
__device__ uint8_t      g_flags[NK];          // 0 none, 1 pos, 2 neg
__device__ unsigned int g_hist[8][NBINS];     // zero-init; cleared by final's last block
__device__ unsigned int g_prefix[8];
__device__ int          g_kk[8];
__device__ int          g_done[8];
__device__ unsigned int g_cnt[8];             // cleared by final's last block
__device__ unsigned int g_cand[8][CAP];
__device__ int          g_cidx[8][CAP];
__device__ unsigned int g_tick;               // ticket (self-resetting)

__device__ __forceinline__ unsigned int fkey(float f) {
    unsigned int u = __float_as_uint(f);
    return (u & 0x80000000u) ? ~u : (u | 0x80000000u);  // order-preserving
}

__device__ __forceinline__ float frcp_approx(float x) {
    float r; asm("rcp.approx.f32 %0, %1;" : "=f"(r) : "f"(x)); return r;
}

__device__ __forceinline__ unsigned int warp_suffix(unsigned int v, int lane) {
    #pragma unroll
    for (int off = 1; off < 32; off <<= 1) {
        unsigned int x = __shfl_down_sync(0xFFFFFFFFu, v, off);
        if (lane + off < 32) v += x;
    }
    return v;
}

// ======== K1: approx max-r fast loop (single-clamp geometry); division-free exact redo ====
__global__ void __launch_bounds__(256, 8) at_main_kernel(
        const float4* __restrict__ anchors,
        const float4* __restrict__ gt_boxes,
        const int*    __restrict__ gt_labels,
        const float*  __restrict__ scores,
        float*        __restrict__ out) {
    __shared__ float4 s_gt[NB * MB];
    __shared__ float  s_S[NB * MB];    // area_g + 1e-8  (fast path)
    __shared__ float  s_ag[NB * MB];   // raw area_g     (exact path)
    __shared__ float  s_lab[NB * MB];

    if (threadIdx.x < NB * MB) {
        const int i = threadIdx.x;
        float4 g = gt_boxes[i];
        s_gt[i]  = g;
        float ag = __fmul_rn(__fsub_rn(g.z, g.x), __fsub_rn(g.w, g.y));
        s_ag[i]  = ag;
        s_S[i]   = __fadd_rn(ag, 1e-8f);
        s_lab[i] = (float)gt_labels[i];
    }
    __syncthreads();

    const int k = blockIdx.x * 256 + threadIdx.x;
    if (k >= KB) return;

    const float4 a = anchors[k];                  // loaded ONCE for all 4 batches
    const float area_a = __fmul_rn(__fsub_rn(a.z, a.x), __fsub_rn(a.w, a.y));

    #pragma unroll 1
    for (int n = 0; n < NB; ++n) {
        const float4* gt = s_gt + n * MB;
        const float*  Sv = s_S  + n * MB;

        // ---- lean fast loop: qmax = max_m inter/S (approx, no argmax) ----
        // Single clamp: inter = max(0,w)*h. If h<0 => inter<=0, same as true q=0
        // for non-overlap; genuinely overlapping boxes are computed exactly as before.
        // Any anomaly only raises qmax into the need_exact band -> exact redo. Safe.
        float qmax = 0.f;                          // true q >= 0 always
        #pragma unroll
        for (int m = 0; m < MB; ++m) {
            float4 g = gt[m];
            float w = fmaxf(__fsub_rn(fminf(a.z, g.z), fmaxf(a.x, g.x)), 0.f);
            float h = __fsub_rn(fminf(a.w, g.w), fmaxf(a.y, g.y));   // unclamped
            float q = __fmul_rn(__fmul_rn(w, h), frcp_approx(area_a + Sv[m]));
            qmax = fmaxf(qmax, q);
        }

        const int idx = n * KB + k;
        uint8_t f;
        float   cls = 0.f;
        float4  r = make_float4(0.f, 0.f, 0.f, 0.f);

        const bool need_exact = (qmax >= R_POS - R_MARGIN) |
                                (fabsf(qmax - R_NEG) <= R_MARGIN);
        if (__builtin_expect(need_exact, 0)) {
            // ---- division-FREE exact redo (cross-mult argmax, reference-exact outside
            //      a 5e-6 near-tie margin; proven R7/R8/R15), ONE fdiv at end ----
            const float* ag_v = s_ag + n * MB;
            float bi, bden; int bm = 0; bool tie = false;
            {
                float4 g = gt[0];
                float w = fmaxf(__fsub_rn(fminf(a.z, g.z), fmaxf(a.x, g.x)), 0.f);
                float h = fmaxf(__fsub_rn(fminf(a.w, g.w), fmaxf(a.y, g.y)), 0.f);
                bi   = __fmul_rn(w, h);
                bden = __fadd_rn(__fsub_rn(__fadd_rn(area_a, ag_v[0]), bi), 1e-8f);
            }
            #pragma unroll 5
            for (int m = 1; m < MB; ++m) {
                float4 g = gt[m];
                float w = fmaxf(__fsub_rn(fminf(a.z, g.z), fmaxf(a.x, g.x)), 0.f);
                float h = fmaxf(__fsub_rn(fminf(a.w, g.w), fmaxf(a.y, g.y)), 0.f);
                float inter = __fmul_rn(w, h);
                float den = __fadd_rn(__fsub_rn(__fadd_rn(area_a, ag_v[m]), inter), 1e-8f);
                float lhs  = __fmul_rn(inter, bden);
                float rhs  = __fmul_rn(bi, den);
                float diff = lhs - rhs;
                tie |= (fabsf(diff) < 5e-6f * fmaxf(lhs, rhs));
                bool better = diff > 0.f;
                bi   = better ? inter : bi;
                bden = better ? den   : bden;
                bm   = better ? m     : bm;
            }
            float max_o;
            if (__builtin_expect(tie, 0)) {
                // ultra-rare: full reference redo with per-m divisions
                max_o = -1.f; bm = 0;
                for (int m = 0; m < MB; ++m) {
                    float4 g = gt[m];
                    float w = fmaxf(__fsub_rn(fminf(a.z, g.z), fmaxf(a.x, g.x)), 0.f);
                    float h = fmaxf(__fsub_rn(fminf(a.w, g.w), fmaxf(a.y, g.y)), 0.f);
                    float inter = __fmul_rn(w, h);
                    float den = __fadd_rn(__fsub_rn(__fadd_rn(area_a, ag_v[m]), inter), 1e-8f);
                    float io  = __fdiv_rn(inter, den);
                    if (io > max_o) { max_o = io; bm = m; }
                }
            } else {
                max_o = __fdiv_rn(bi, bden);   // exact reference max IoU
            }
            const bool pos = max_o >= 0.7f;
            const bool neg = max_o <  0.3f;
            f = pos ? (uint8_t)1 : (neg ? (uint8_t)2 : (uint8_t)0);
            if (pos) {
                cls = s_lab[n * MB + bm];
                const float aw  = a.z - a.x,        ah  = a.w - a.y;
                const float acx = a.x + 0.5f * aw,  acy = a.y + 0.5f * ah;
                float4 g  = gt[bm];
                float gw  = g.z - g.x,       gh  = g.w - g.y;
                float gcx = g.x + 0.5f * gw, gcy = g.y + 0.5f * gh;
                r.x = (gcx - acx) / aw;
                r.y = (gcy - acy) / ah;
                r.z = logf(gw / aw);
                r.w = logf(gh / ah);
            }
        } else {
            f = (qmax < R_NEG) ? (uint8_t)2 : (uint8_t)0;
        }

        g_flags[idx] = f;
        out[idx] = cls;
        ((float4*)(out + NK))[idx] = r;

        if (f) {  // fused 12-bit radix histogram (top 12 key bits)
            unsigned int key = fkey(__ldg(&scores[idx]));
            atomicAdd(&g_hist[n * 2 + (int)(f - 1)][key >> 20], 1u);
        }
    }
}

// ======== K2: pick 12-bit threshold bin per selection (register-resident pick) ========
__global__ void __launch_bounds__(256) at_scanA_kernel() {
    cudaGridDependencySynchronize();        // PDL: wait for at_main's hist
    const int sel = blockIdx.x;
    const int t   = threadIdx.x;            // 256 threads × 16 bins
    const unsigned int* __restrict__ h = g_hist[sel];
    __shared__ unsigned int s[256];

    unsigned int v[16];
    const int base = t * 16;
    unsigned int sum = 0;
    #pragma unroll
    for (int i = 0; i < 16; ++i) { v[i] = __ldg(&h[base + i]); sum += v[i]; }
    s[t] = sum;
    __syncthreads();
    #pragma unroll
    for (int off = 1; off < 256; off <<= 1) {   // inclusive suffix scan
        unsigned int x = (t + off < 256) ? s[t + off] : 0u;
        __syncthreads();
        s[t] += x;
        __syncthreads();
    }
    const unsigned int total = s[0];
    const unsigned int above = s[t] - sum;      // strictly above this chunk
    if (t == 0) g_done[sel] = (total < SELK);
    if (total >= SELK && above < SELK && above + sum >= SELK) {   // exactly one thread
        unsigned int cum = above;
        #pragma unroll
        for (int b = 15; b >= 0; --b) {
            unsigned int c = v[b];
            if (cum + c >= SELK) {
                g_prefix[sel] = (unsigned int)(base + b);
                g_kk[sel]     = (int)(SELK - cum);
                break;
            }
            cum += c;
        }
    }
}

// warp-level topbin over 1024 smem bins: lane owns bins [lane*32, lane*32+32).
__device__ __forceinline__ void warp_topbin1024(const unsigned int* h, unsigned int kk,
                                                int lane, unsigned int& bin_out,
                                                unsigned int& kk_out) {
    const int base = lane * 32;
    unsigned int v[32]; unsigned int sum = 0;
    #pragma unroll
    for (int i = 0; i < 32; ++i) { v[i] = h[base + i]; sum += v[i]; }
    unsigned int suf = warp_suffix(sum, lane);
    unsigned int above = suf - sum;                 // strictly above this lane's chunk
    bool owner = (above < kk) && (above + sum >= kk);
    unsigned int my_bin = 0, my_kk = 0;
    if (owner) {
        unsigned int cum = above;
        #pragma unroll
        for (int b = 31; b >= 0; --b) {
            if (cum + v[b] >= kk) { my_bin = (unsigned int)(base + b); my_kk = kk - cum; break; }
            cum += v[b];
        }
    }
    unsigned int mask = __ballot_sync(0xFFFFFFFFu, owner);
    int src = __ffs(mask) - 1;
    bin_out = __shfl_sync(0xFFFFFFFFu, my_bin, src);
    kk_out  = __shfl_sync(0xFFFFFFFFu, my_kk,  src);
}

// ======== K3: weights + candidate gather; last block = per-warp exact select + cleanup ====
__global__ void __launch_bounds__(256) at_final_kernel(const float* __restrict__ scores,
                                                       float* __restrict__ out) {
    cudaGridDependencySynchronize();        // PDL: wait for at_scanA's prefixes
    __shared__ unsigned int s_hist2[8][1024];   // 32KB: one 1024-bin hist per selection
    __shared__ int s_last;

    const int n = blockIdx.y;
    const int k = blockIdx.x * 256 + threadIdx.x;
    bool pushed = false;
    if (k < KB) {
        const int idx = n * KB + k;
        const uint8_t f = g_flags[idx];
        float cw = 0.f, rw = 0.f;
        if (f) {
            const int sel = n * 2 + (int)(f - 1);
            if (g_done[sel]) {
                cw = 1.f; rw = (f == 1) ? 1.f : 0.f;       // take all members
            } else {
                const unsigned int key = fkey(__ldg(&scores[idx]));
                const unsigned int hb  = key >> 20;
                const unsigned int pfx = g_prefix[sel];
                if (hb > pfx) {
                    cw = 1.f; rw = (f == 1) ? 1.f : 0.f;
                } else if (hb == pfx) {
                    unsigned int slot = atomicAdd(&g_cnt[sel], 1u);
                    if (slot < CAP) { g_cand[sel][slot] = key; g_cidx[sel][slot] = idx; }
                    pushed = true;
                }
            }
        }
        out[5 * NK + idx] = cw;
        out[6 * NK + idx] = rw;
    }
    // RARE fence: only candidate-pushing threads (~hundreds chip-wide) pay the membar.
    if (pushed) __threadfence();
    __syncthreads();
    if (threadIdx.x == 0) {
        unsigned int old = atomicAdd(&g_tick, 1u);
        s_last = (old == gridDim.x * gridDim.y - 1u);
    }
    __syncthreads();
    if (!s_last) return;
    __threadfence();

    // ---- last block: 8 warps, one selection each (no cross-warp syncs needed) ----
    const int lane = threadIdx.x & 31;
    const int sel  = threadIdx.x >> 5;
    const int c = g_done[sel] ? 0 : (int)min(g_cnt[sel], (unsigned int)CAP);
    if (c > 0) {
        unsigned int* h = s_hist2[sel];
        const unsigned int kk = (unsigned int)g_kk[sel];

        // pass 1: bits [10,20)
        #pragma unroll 8
        for (int i = lane; i < 1024; i += 32) h[i] = 0u;
        __syncwarp();
        for (int i = lane; i < c; i += 32)
            atomicAdd(&h[(g_cand[sel][i] >> 10) & 1023u], 1u);
        __syncwarp();
        unsigned int b1, k2;
        warp_topbin1024(h, kk, lane, b1, k2);

        // pass 2: bits [0,10) among candidates with mid bits == b1
        #pragma unroll 8
        for (int i = lane; i < 1024; i += 32) h[i] = 0u;
        __syncwarp();
        for (int i = lane; i < c; i += 32) {
            unsigned int key = g_cand[sel][i];
            if (((key >> 10) & 1023u) == b1) atomicAdd(&h[key & 1023u], 1u);
        }
        __syncwarp();
        unsigned int b0, dummy;
        warp_topbin1024(h, k2, lane, b0, dummy);

        // write in-bin winners (low-20 bits >= exact kth-largest low bits)
        const unsigned int thr20 = (b1 << 10) | b0;
        const float rwv = (sel & 1) ? 0.f : 1.f;     // even sel = positives
        for (int i = lane; i < c; i += 32) {
            if ((g_cand[sel][i] & 0xFFFFFu) >= thr20) {
                int idx = g_cidx[sel][i];
                out[5 * NK + idx] = 1.f;
                out[6 * NK + idx] = rwv;
            }
        }
    }

    // ---- cleanup for next graph replay ----
    __syncthreads();
    for (int i = threadIdx.x; i < 8 * NBINS; i += 256) ((unsigned int*)g_hist)[i] = 0u;
    if (threadIdx.x < 8) g_cnt[threadIdx.x] = 0u;
    if (threadIdx.x == 0) g_tick = 0u;
}

// ---------------- launch (3 kernels, PDL chain) ----------------
extern "C" void kernel_launch(void* const* d_in, const int* in_sizes, int n_in,
                              void* d_out, int out_size) {
    const float4* anchors  = (const float4*)d_in[0];   // (K,4) f32
    const float*  scores   = (const float*) d_in[1];   // (N,K) f32
    const float4* gt_boxes = (const float4*)d_in[2];   // (N,M,4) f32
    const int*    gt_lab   = (const int*)   d_in[3];   // (N,M) i32
    float* out = (float*)d_out;  // [cls_t | reg_t | cls_w | reg_w]

    const int GB = (KB + 255) / 256;   // 938
    at_main_kernel<<<GB, 256>>>(anchors, gt_boxes, gt_lab, scores, out);

    cudaLaunchAttribute attr;
    attr.id = cudaLaunchAttributeProgrammaticStreamSerialization;
    attr.val.programmaticStreamSerializationAllowed = 1;

    cudaLaunchConfig_t cfg = {};
    cfg.attrs = &attr;
    cfg.numAttrs = 1;
    cfg.blockDim = dim3(256, 1, 1);

    cfg.gridDim = dim3(8, 1, 1);
    cudaLaunchKernelEx(&cfg, at_scanA_kernel);

    cfg.gridDim = dim3(GB, NB, 1);
    cudaLaunchKernelEx(&cfg, at_final_kernel, scores, out);
}